// round 10
// baseline (speedup 1.0000x reference)
#include <cuda_runtime.h>
#include <math.h>

#define BB  64
#define LCC 512
#define LQQ 64
#define DD  256

// ---------------------------------------------------------------------------
// tf32 mma (m16n8k8, row.col, fp32 accum) — operands are RAW fp32 bits
// ---------------------------------------------------------------------------
__device__ __forceinline__ void mma8(float& d0, float& d1, float& d2, float& d3,
                                     unsigned a0, unsigned a1, unsigned a2, unsigned a3,
                                     unsigned b0, unsigned b1) {
    asm("mma.sync.aligned.m16n8k8.row.col.f32.tf32.tf32.f32 "
        "{%0,%1,%2,%3},{%4,%5,%6,%7},{%8,%9},{%0,%1,%2,%3};"
        : "+f"(d0), "+f"(d1), "+f"(d2), "+f"(d3)
        : "r"(a0), "r"(a1), "r"(a2), "r"(a3), "r"(b0), "r"(b1));
}
__device__ __forceinline__ unsigned sm2u(const void* p) {
    unsigned r;
    asm("{.reg .u64 t; cvta.to.shared.u64 t, %1; cvt.u32.u64 %0, t;}" : "=r"(r) : "l"(p));
    return r;
}
#define CPA16(dst, src) asm volatile("cp.async.ca.shared.global [%0], [%1], 16;" :: "r"(dst), "l"(src))
#define CPCOMMIT()      asm volatile("cp.async.commit_group;")
#define CPWAIT1()       asm volatile("cp.async.wait_group 1;")
#define CPWAIT0()       asm volatile("cp.async.wait_group 0;")

// Scratch (device globals; no allocation allowed)
__device__ float g_Qp[(size_t)BB * LQQ * DD];            // wi*q + wc
__device__ float g_t[BB * LQQ];                          // <q,wq> + bias
__device__ float g_S1[(size_t)BB * LCC * LQQ];           // row-softmax(S)
__device__ float g_rs[BB * LCC];                         // unshifted row expsums
__device__ float g_cpart[4 * BB * LQQ];                  // per-i-block col expsum partials
__device__ float g_C2[(size_t)BB * LQQ * DD];            // S2^T @ contex

// ---------------------------------------------------------------------------
// K0: Q'[b,j,d] = wi[d]*q[b,j,d] + wc[d];  t[b,j] = <q[b,j], wq> + bias
// ---------------------------------------------------------------------------
__global__ void k0_prep(const float* __restrict__ q,
                        const float* __restrict__ W,
                        const float* __restrict__ bias) {
    const int bj = blockIdx.x;
    const int d  = threadIdx.x;
    const float qv = q[(size_t)bj * DD + d];
    g_Qp[(size_t)bj * DD + d] = fmaf(W[2 * DD + d], qv, W[DD + d]);

    float v = qv * W[d];
    #pragma unroll
    for (int o = 16; o > 0; o >>= 1) v += __shfl_xor_sync(0xffffffffu, v, o);
    __shared__ float red[8];
    if ((threadIdx.x & 31) == 0) red[threadIdx.x >> 5] = v;
    __syncthreads();
    if (threadIdx.x == 0) {
        float s = 0.f;
        #pragma unroll
        for (int i = 0; i < 8; i++) s += red[i];
        g_t[bj] = s + bias[0];
    }
}

// ---------------------------------------------------------------------------
// K1: S = contex @ Q'^T + t via raw-fp32 tf32 mma, 3-stage cp.async pipeline.
// Block 128(i) x 64(j), 256 thr = 8 warps (16x64), K=256. grid=(4, B)
// Outputs: S1 (row softmax), rs (row expsums), col expsum partials.
// ---------------------------------------------------------------------------
__global__ void __launch_bounds__(256, 2) k1_score(const float* __restrict__ contex) {
    const int b  = blockIdx.y;
    const int i0 = blockIdx.x * 128;
    const int tid = threadIdx.x;
    const int warp = tid >> 5, lane = tid & 31;
    const int g = lane >> 2, t = lane & 3;
    const int wm = warp * 16;

    extern __shared__ float sm[];
    float* As   = sm;                 // 3 x 128 x 36 = 13824
    float* Bs   = sm + 13824;         // 3 x 64 x 36  = 6912
    float* ts   = sm + 20736;         // 64
    float* scol = sm + 20800;         // 8 x 64 = 512
    if (tid < 64) ts[tid] = g_t[b * LQQ + tid];

    const float* Cb = contex + (size_t)b * LCC * DD;
    const float* Qp = g_Qp  + (size_t)b * LQQ * DD;

    const int alr = tid >> 1, ako = (tid & 1) * 16;   // A: 4x16B per stage
    const int bjr = tid >> 2, bko = (tid & 3) * 8;    // B: 2x16B per stage
    const unsigned smu = sm2u(sm);

    auto cpStage = [&](int s) {
        const int buf = s % 3;
        const float* ga = &Cb[(size_t)(i0 + alr) * DD + s * 32 + ako];
        unsigned da = smu + (unsigned)((buf * 128 + alr) * 36 + ako) * 4u;
        CPA16(da,      ga);     CPA16(da + 16, ga + 4);
        CPA16(da + 32, ga + 8); CPA16(da + 48, ga + 12);
        const float* gb = &Qp[(size_t)bjr * DD + s * 32 + bko];
        unsigned db = smu + (unsigned)(13824 + (buf * 64 + bjr) * 36 + bko) * 4u;
        CPA16(db, gb); CPA16(db + 16, gb + 4);
        CPCOMMIT();
    };

    float acc[8][4];
    #pragma unroll
    for (int nt = 0; nt < 8; nt++)
        #pragma unroll
        for (int r = 0; r < 4; r++) acc[nt][r] = 0.f;

    cpStage(0); cpStage(1);

    #pragma unroll
    for (int it = 0; it < 8; it++) {
        if (it < 7) { CPWAIT1(); } else { CPWAIT0(); }
        __syncthreads();
        if (it + 2 < 8) cpStage(it + 2);
        const float* Ab = As + (size_t)(it % 3) * 128 * 36;
        const float* Bb = Bs + (size_t)(it % 3) * 64 * 36;
        #pragma unroll
        for (int kc = 0; kc < 32; kc += 8) {
            unsigned a0 = *(const unsigned*)&Ab[(size_t)(wm + g) * 36 + kc + t];
            unsigned a1 = *(const unsigned*)&Ab[(size_t)(wm + 8 + g) * 36 + kc + t];
            unsigned a2 = *(const unsigned*)&Ab[(size_t)(wm + g) * 36 + kc + t + 4];
            unsigned a3 = *(const unsigned*)&Ab[(size_t)(wm + 8 + g) * 36 + kc + t + 4];
            #pragma unroll
            for (int nt = 0; nt < 8; nt++) {
                unsigned b0 = *(const unsigned*)&Bb[(size_t)(nt * 8 + g) * 36 + kc + t];
                unsigned b1 = *(const unsigned*)&Bb[(size_t)(nt * 8 + g) * 36 + kc + t + 4];
                mma8(acc[nt][0], acc[nt][1], acc[nt][2], acc[nt][3],
                     a0, a1, a2, a3, b0, b1);
            }
        }
        __syncthreads();
    }

    // ---- epilogue: +t[j], col expsums, row softmax -> S1, row sums -> rs ----
    float* S1b = g_S1 + (size_t)b * LCC * LQQ;
    float cs[16];
    #pragma unroll
    for (int c = 0; c < 16; c++) cs[c] = 0.f;

    #pragma unroll
    for (int h = 0; h < 2; h++) {
        const int i = i0 + wm + h * 8 + g;
        float s[16];
        #pragma unroll
        for (int nt = 0; nt < 8; nt++) {
            s[2 * nt]     = acc[nt][2 * h]     + ts[nt * 8 + 2 * t];
            s[2 * nt + 1] = acc[nt][2 * h + 1] + ts[nt * 8 + 2 * t + 1];
        }
        #pragma unroll
        for (int c = 0; c < 16; c++) cs[c] += __expf(s[c]);
        float m = s[0];
        #pragma unroll
        for (int c = 1; c < 16; c++) m = fmaxf(m, s[c]);
        m = fmaxf(m, __shfl_xor_sync(0xffffffffu, m, 1));
        m = fmaxf(m, __shfl_xor_sync(0xffffffffu, m, 2));
        float e[16], sum = 0.f;
        #pragma unroll
        for (int c = 0; c < 16; c++) { e[c] = __expf(s[c] - m); sum += e[c]; }
        sum += __shfl_xor_sync(0xffffffffu, sum, 1);
        sum += __shfl_xor_sync(0xffffffffu, sum, 2);
        const float inv = 1.f / sum;
        #pragma unroll
        for (int nt = 0; nt < 8; nt++) {
            float2 o = make_float2(e[2 * nt] * inv, e[2 * nt + 1] * inv);
            *(float2*)&S1b[(size_t)i * LQQ + nt * 8 + 2 * t] = o;
        }
        if (t == 0) g_rs[b * LCC + i] = sum * __expf(m);
    }
    #pragma unroll
    for (int c = 0; c < 16; c++) {
        cs[c] += __shfl_xor_sync(0xffffffffu, cs[c], 4);
        cs[c] += __shfl_xor_sync(0xffffffffu, cs[c], 8);
        cs[c] += __shfl_xor_sync(0xffffffffu, cs[c], 16);
    }
    if (g == 0) {
        #pragma unroll
        for (int c = 0; c < 16; c++) {
            const int j = (c >> 1) * 8 + 2 * t + (c & 1);
            scol[warp * 64 + j] = cs[c];
        }
    }
    __syncthreads();
    if (tid < 64) {
        float p = 0.f;
        #pragma unroll
        for (int w = 0; w < 8; w++) p += scol[w * 64 + tid];
        g_cpart[blockIdx.x * (BB * LQQ) + b * LQQ + tid] = p;
    }
}

// ---------------------------------------------------------------------------
// K3: C2 = S2^T @ contex, full K=512.  S2[i,j] = S1[i,j]*rs_i*inv_j built on
// the A-fill from L2-hot S1 (no exp).  inv combine folded into prologue.
// Block 64(j) x 64(n), 512 thr = 16 warps 4(m)x4(n), warp tile 16x16.
// A stored [k][j] so the transpose-fill is one float4 STS. grid=(4, B)
// ---------------------------------------------------------------------------
__global__ void __launch_bounds__(512, 2) k3_c2(const float* __restrict__ contex) {
    const int b   = blockIdx.y;
    const int n0  = blockIdx.x * 64;
    const int tid = threadIdx.x;
    const int warp = tid >> 5, lane = tid & 31;
    const int g = lane >> 2, t = lane & 3;
    const int wm = (warp & 3) * 16;
    const int wn = (warp >> 2) * 16;

    extern __shared__ float sm3[];
    float* As   = sm3;                     // 2 x 32 x 68 [k=i][j]
    float* Bs   = sm3 + 4352;              // 3 x 32 x 72 [k][n]
    float* rssm = sm3 + 4352 + 6912;       // 512
    float* sinv = rssm + 512;              // 64

    const float* S1b = g_S1 + (size_t)b * LCC * LQQ;
    const float* Cb  = contex + (size_t)b * LCC * DD;

    rssm[tid] = g_rs[b * LCC + tid];
    if (tid < 64) {
        const int idx = b * LQQ + tid;
        float s = g_cpart[idx] + g_cpart[BB * LQQ + idx]
                + g_cpart[2 * BB * LQQ + idx] + g_cpart[3 * BB * LQQ + idx];
        sinv[tid] = 1.f / s;
    }
    __syncthreads();

    const int iloc = tid >> 4, jo = (tid & 15) * 4;   // A fill: 32 rows x 64 j
    const float4 inv4 = *(const float4*)&sinv[jo];
    const unsigned smu = sm2u(sm3);

    auto cpB = [&](int s) {
        const int buf = s % 3;
        const float* c = &Cb[(size_t)(s * 32 + iloc) * DD + n0 + jo];
        unsigned db = smu + (unsigned)(4352 + (buf * 32 + iloc) * 72 + jo) * 4u;
        CPA16(db, c);
        CPCOMMIT();
    };

    float4 ra; float rsv;
    auto ldA = [&](int s) {
        ra  = *(const float4*)&S1b[(size_t)(s * 32 + iloc) * LQQ + jo];
        rsv = rssm[s * 32 + iloc];
    };
    auto stA = [&](int s) {
        float4 v = make_float4(ra.x * rsv * inv4.x, ra.y * rsv * inv4.y,
                               ra.z * rsv * inv4.z, ra.w * rsv * inv4.w);
        *(float4*)&As[(size_t)((s & 1) * 32 + iloc) * 68 + jo] = v;
    };

    float acc[2][4];
    #pragma unroll
    for (int nt = 0; nt < 2; nt++)
        #pragma unroll
        for (int r = 0; r < 4; r++) acc[nt][r] = 0.f;

    cpB(0); cpB(1);
    ldA(0); stA(0);

    #pragma unroll 4
    for (int it = 0; it < 16; it++) {
        if (it < 15) { CPWAIT1(); } else { CPWAIT0(); }
        __syncthreads();
        if (it + 2 < 16) cpB(it + 2);
        if (it < 15) ldA(it + 1);

        const float* Ab = As + (size_t)(it & 1) * 32 * 68;
        const float* Bb = Bs + (size_t)(it % 3) * 32 * 72;
        #pragma unroll
        for (int kc = 0; kc < 32; kc += 8) {
            unsigned a0 = *(const unsigned*)&Ab[(size_t)(kc + t) * 68 + wm + g];
            unsigned a1 = *(const unsigned*)&Ab[(size_t)(kc + t) * 68 + wm + 8 + g];
            unsigned a2 = *(const unsigned*)&Ab[(size_t)(kc + t + 4) * 68 + wm + g];
            unsigned a3 = *(const unsigned*)&Ab[(size_t)(kc + t + 4) * 68 + wm + 8 + g];
            #pragma unroll
            for (int nt = 0; nt < 2; nt++) {
                const int n = wn + nt * 8 + g;
                unsigned b0 = *(const unsigned*)&Bb[(size_t)(kc + t) * 72 + n];
                unsigned b1 = *(const unsigned*)&Bb[(size_t)(kc + t + 4) * 72 + n];
                mma8(acc[nt][0], acc[nt][1], acc[nt][2], acc[nt][3],
                     a0, a1, a2, a3, b0, b1);
            }
        }
        if (it < 15) stA(it + 1);
        __syncthreads();
    }

    float* outp = g_C2 + (size_t)b * LQQ * DD;
    #pragma unroll
    for (int h = 0; h < 2; h++) {
        const int j = wm + h * 8 + g;
        #pragma unroll
        for (int nt = 0; nt < 2; nt++) {
            float2 o = make_float2(acc[nt][2 * h], acc[nt][2 * h + 1]);
            *(float2*)&outp[(size_t)j * DD + n0 + wn + nt * 8 + 2 * t] = o;
        }
    }
}

// ---------------------------------------------------------------------------
// K4: A = S1 @ question, Bm = S1 @ C2, dual-B per chunk via 2-stage cp.async.
// Block 64(i), 256 thr = 8 warps 4(m)x2(n), warp tile 16x32 per GEMM.
// fused output: out[b,i] = [contex | A | contex*A | contex*Bm]. grid=(8, B)
// ---------------------------------------------------------------------------
__global__ void __launch_bounds__(256, 2) k4_out(const float* __restrict__ contex,
                                                 const float* __restrict__ question,
                                                 float* __restrict__ out) {
    const int b  = blockIdx.y;
    const int i0 = blockIdx.x * 64;
    const int tid = threadIdx.x;
    const int warp = tid >> 5, lane = tid & 31;
    const int g = lane >> 2, t = lane & 3;
    const int wm = (warp & 3) * 16;
    const int wn = (warp >> 2) * 32;

    extern __shared__ float sm4[];
    float* As = sm4;                        // 64 x 68 [i][j] persistent
    float* Bt = sm4 + 64 * 68;              // 2 buf x 2 tiles x 64 x 72

    const float* S1b = g_S1 + (size_t)b * LCC * LQQ;
    {   // fill A once (raw fp32): 64 rows x 64 j
        const int lr = tid >> 2, jo = (tid & 3) * 16;
        const float* src = &S1b[(size_t)(i0 + lr) * LQQ + jo];
        float* dst = &As[(size_t)lr * 68 + jo];
        *(float4*)&dst[0]  = *(const float4*)&src[0];
        *(float4*)&dst[4]  = *(const float4*)&src[4];
        *(float4*)&dst[8]  = *(const float4*)&src[8];
        *(float4*)&dst[12] = *(const float4*)&src[12];
    }

    const float* Cb = contex   + (size_t)b * LCC * DD;
    const float* Qb = question + (size_t)b * LQQ * DD;
    const float* P  = g_C2     + (size_t)b * LQQ * DD;
    float* outb = out + (size_t)b * LCC * 1024;

    const int bjr = tid >> 2, boff = (tid & 3) * 16;   // 64 rows x 4 thr/row
    const unsigned smu = sm2u(sm4);

    auto cpB = [&](int chunk) {
        const int buf = chunk & 1;
        const int c0 = chunk * 64;
        const float* q = &Qb[(size_t)bjr * DD + c0 + boff];
        unsigned dq = smu + (unsigned)(64 * 68 + (buf * 128 + bjr) * 72 + boff) * 4u;
        CPA16(dq,      q);     CPA16(dq + 16, q + 4);
        CPA16(dq + 32, q + 8); CPA16(dq + 48, q + 12);
        const float* p = &P[(size_t)bjr * DD + c0 + boff];
        unsigned dc = smu + (unsigned)(64 * 68 + (buf * 128 + 64 + bjr) * 72 + boff) * 4u;
        CPA16(dc,      p);     CPA16(dc + 16, p + 4);
        CPA16(dc + 32, p + 8); CPA16(dc + 48, p + 12);
        CPCOMMIT();
    };

    cpB(0);

    #pragma unroll
    for (int chunk = 0; chunk < 4; chunk++) {
        const int buf = chunk & 1;
        const int c0 = chunk * 64;
        if (chunk < 3) cpB(chunk + 1);
        if (chunk < 3) { CPWAIT1(); } else { CPWAIT0(); }
        __syncthreads();

        float accq[4][4], accc[4][4];
        #pragma unroll
        for (int nt = 0; nt < 4; nt++)
            #pragma unroll
            for (int r = 0; r < 4; r++) { accq[nt][r] = 0.f; accc[nt][r] = 0.f; }

        const float* Bq = Bt + (size_t)buf * 128 * 72;
        const float* Bc = Bq + 64 * 72;
        #pragma unroll
        for (int kc = 0; kc < 64; kc += 8) {
            unsigned a0 = *(const unsigned*)&As[(size_t)(wm + g) * 68 + kc + t];
            unsigned a1 = *(const unsigned*)&As[(size_t)(wm + 8 + g) * 68 + kc + t];
            unsigned a2 = *(const unsigned*)&As[(size_t)(wm + g) * 68 + kc + t + 4];
            unsigned a3 = *(const unsigned*)&As[(size_t)(wm + 8 + g) * 68 + kc + t + 4];
            #pragma unroll
            for (int nt = 0; nt < 4; nt++) {
                const int n = wn + nt * 8 + g;
                unsigned q0 = *(const unsigned*)&Bq[(size_t)(kc + t) * 72 + n];
                unsigned q1 = *(const unsigned*)&Bq[(size_t)(kc + t + 4) * 72 + n];
                mma8(accq[nt][0], accq[nt][1], accq[nt][2], accq[nt][3],
                     a0, a1, a2, a3, q0, q1);
                unsigned c0r = *(const unsigned*)&Bc[(size_t)(kc + t) * 72 + n];
                unsigned c1r = *(const unsigned*)&Bc[(size_t)(kc + t + 4) * 72 + n];
                mma8(accc[nt][0], accc[nt][1], accc[nt][2], accc[nt][3],
                     a0, a1, a2, a3, c0r, c1r);
            }
        }

        #pragma unroll
        for (int h = 0; h < 2; h++) {
            const int i = i0 + wm + h * 8 + g;
            const float* crow = &Cb[(size_t)i * DD];
            float* orow = &outb[(size_t)i * 1024];
            #pragma unroll
            for (int nt = 0; nt < 4; nt++) {
                const int col = c0 + wn + nt * 8 + 2 * t;
                float2 cv = *(const float2*)&crow[col];
                float2 av = make_float2(accq[nt][2 * h], accq[nt][2 * h + 1]);
                float2 bv = make_float2(accc[nt][2 * h], accc[nt][2 * h + 1]);
                float2 pa = make_float2(cv.x * av.x, cv.y * av.y);
                float2 pb = make_float2(cv.x * bv.x, cv.y * bv.y);
                *(float2*)&orow[col]       = cv;
                *(float2*)&orow[256 + col] = av;
                *(float2*)&orow[512 + col] = pa;
                *(float2*)&orow[768 + col] = pb;
            }
        }
        __syncthreads();
    }
}

// ---------------------------------------------------------------------------
extern "C" void kernel_launch(void* const* d_in, const int* in_sizes, int n_in,
                              void* d_out, int out_size) {
    const float* contex   = (const float*)d_in[0];
    const float* question = (const float*)d_in[1];
    const float* W        = (const float*)d_in[2];
    const float* bias     = (const float*)d_in[3];
    float* out = (float*)d_out;

    const int k1smem = 21312 * (int)sizeof(float);                          // 85248
    const int k3smem = (4352 + 6912 + 512 + 64) * (int)sizeof(float);       // 47360
    const int k4smem = (64 * 68 + 2 * 2 * 64 * 72) * (int)sizeof(float);    // 91136
    cudaFuncSetAttribute(k1_score, cudaFuncAttributeMaxDynamicSharedMemorySize, k1smem);
    cudaFuncSetAttribute(k3_c2,    cudaFuncAttributeMaxDynamicSharedMemorySize, k3smem);
    cudaFuncSetAttribute(k4_out,   cudaFuncAttributeMaxDynamicSharedMemorySize, k4smem);

    k0_prep<<<BB * LQQ, 256>>>(question, W, bias);
    k1_score<<<dim3(4, BB), 256, k1smem>>>(contex);
    k3_c2<<<dim3(4, BB), 512, k3smem>>>(contex);
    k4_out<<<dim3(8, BB), 256, k4smem>>>(contex, question, out);
}

// round 11
// speedup vs baseline: 1.0067x; 1.0067x over previous
#include <cuda_runtime.h>
#include <math.h>

#define BB  64
#define LCC 512
#define LQQ 64
#define DD  256

// ---------------------------------------------------------------------------
// tf32 mma (m16n8k8, row.col, fp32 accum) — operands are RAW fp32 bits
// ---------------------------------------------------------------------------
__device__ __forceinline__ void mma8(float& d0, float& d1, float& d2, float& d3,
                                     unsigned a0, unsigned a1, unsigned a2, unsigned a3,
                                     unsigned b0, unsigned b1) {
    asm("mma.sync.aligned.m16n8k8.row.col.f32.tf32.tf32.f32 "
        "{%0,%1,%2,%3},{%4,%5,%6,%7},{%8,%9},{%0,%1,%2,%3};"
        : "+f"(d0), "+f"(d1), "+f"(d2), "+f"(d3)
        : "r"(a0), "r"(a1), "r"(a2), "r"(a3), "r"(b0), "r"(b1));
}
__device__ __forceinline__ unsigned sm2u(const void* p) {
    unsigned r;
    asm("{.reg .u64 t; cvta.to.shared.u64 t, %1; cvt.u32.u64 %0, t;}" : "=r"(r) : "l"(p));
    return r;
}
#define CPA16(dst, src) asm volatile("cp.async.ca.shared.global [%0], [%1], 16;" :: "r"(dst), "l"(src))
#define CPCOMMIT()      asm volatile("cp.async.commit_group;")
#define CPWAIT1()       asm volatile("cp.async.wait_group 1;")
#define CPWAIT0()       asm volatile("cp.async.wait_group 0;")

// Scratch (device globals; no allocation allowed)
__device__ float g_Qp[(size_t)BB * LQQ * DD];            // wi*q + wc
__device__ float g_t[BB * LQQ];                          // <q,wq> + bias
__device__ float g_S1[(size_t)BB * LCC * LQQ];           // row-softmax(S)
__device__ float g_rs[BB * LCC];                         // unshifted row expsums
__device__ float g_cpart[4 * BB * LQQ];                  // per-i-block col expsum partials
__device__ float g_C2[(size_t)BB * LQQ * DD];            // S2^T @ contex

// ---------------------------------------------------------------------------
// K0: Q'[b,j,d] = wi[d]*q[b,j,d] + wc[d];  t[b,j] = <q[b,j], wq> + bias
// ---------------------------------------------------------------------------
__global__ void k0_prep(const float* __restrict__ q,
                        const float* __restrict__ W,
                        const float* __restrict__ bias) {
    const int bj = blockIdx.x;
    const int d  = threadIdx.x;
    const float qv = q[(size_t)bj * DD + d];
    g_Qp[(size_t)bj * DD + d] = fmaf(W[2 * DD + d], qv, W[DD + d]);

    float v = qv * W[d];
    #pragma unroll
    for (int o = 16; o > 0; o >>= 1) v += __shfl_xor_sync(0xffffffffu, v, o);
    __shared__ float red[8];
    if ((threadIdx.x & 31) == 0) red[threadIdx.x >> 5] = v;
    __syncthreads();
    if (threadIdx.x == 0) {
        float s = 0.f;
        #pragma unroll
        for (int i = 0; i < 8; i++) s += red[i];
        g_t[bj] = s + bias[0];
    }
}

// ---------------------------------------------------------------------------
// K1: S = contex @ Q'^T + t via raw-fp32 tf32 mma, 3-stage cp.async pipeline.
// Block 128(i) x 64(j), 256 thr = 8 warps (16x64), K=256. grid=(4, B)
// Outputs: S1 (row softmax), rs (row expsums), col expsum partials.
// ---------------------------------------------------------------------------
__global__ void __launch_bounds__(256, 2) k1_score(const float* __restrict__ contex) {
    const int b  = blockIdx.y;
    const int i0 = blockIdx.x * 128;
    const int tid = threadIdx.x;
    const int warp = tid >> 5, lane = tid & 31;
    const int g = lane >> 2, t = lane & 3;
    const int wm = warp * 16;

    extern __shared__ float sm[];
    float* As   = sm;                 // 3 x 128 x 36 = 13824
    float* Bs   = sm + 13824;         // 3 x 64 x 36  = 6912
    float* ts   = sm + 20736;         // 64
    float* scol = sm + 20800;         // 8 x 64 = 512
    if (tid < 64) ts[tid] = g_t[b * LQQ + tid];

    const float* Cb = contex + (size_t)b * LCC * DD;
    const float* Qp = g_Qp  + (size_t)b * LQQ * DD;

    const int alr = tid >> 1, ako = (tid & 1) * 16;   // A: 4x16B per stage
    const int bjr = tid >> 2, bko = (tid & 3) * 8;    // B: 2x16B per stage
    const unsigned smu = sm2u(sm);

    auto cpStage = [&](int s) {
        const int buf = s % 3;
        const float* ga = &Cb[(size_t)(i0 + alr) * DD + s * 32 + ako];
        unsigned da = smu + (unsigned)((buf * 128 + alr) * 36 + ako) * 4u;
        CPA16(da,      ga);     CPA16(da + 16, ga + 4);
        CPA16(da + 32, ga + 8); CPA16(da + 48, ga + 12);
        const float* gb = &Qp[(size_t)bjr * DD + s * 32 + bko];
        unsigned db = smu + (unsigned)(13824 + (buf * 64 + bjr) * 36 + bko) * 4u;
        CPA16(db, gb); CPA16(db + 16, gb + 4);
        CPCOMMIT();
    };

    float acc[8][4];
    #pragma unroll
    for (int nt = 0; nt < 8; nt++)
        #pragma unroll
        for (int r = 0; r < 4; r++) acc[nt][r] = 0.f;

    cpStage(0); cpStage(1);

    #pragma unroll
    for (int it = 0; it < 8; it++) {
        if (it < 7) { CPWAIT1(); } else { CPWAIT0(); }
        __syncthreads();
        if (it + 2 < 8) cpStage(it + 2);
        const float* Ab = As + (size_t)(it % 3) * 128 * 36;
        const float* Bb = Bs + (size_t)(it % 3) * 64 * 36;
        #pragma unroll
        for (int kc = 0; kc < 32; kc += 8) {
            unsigned a0 = *(const unsigned*)&Ab[(size_t)(wm + g) * 36 + kc + t];
            unsigned a1 = *(const unsigned*)&Ab[(size_t)(wm + 8 + g) * 36 + kc + t];
            unsigned a2 = *(const unsigned*)&Ab[(size_t)(wm + g) * 36 + kc + t + 4];
            unsigned a3 = *(const unsigned*)&Ab[(size_t)(wm + 8 + g) * 36 + kc + t + 4];
            #pragma unroll
            for (int nt = 0; nt < 8; nt++) {
                unsigned b0 = *(const unsigned*)&Bb[(size_t)(nt * 8 + g) * 36 + kc + t];
                unsigned b1 = *(const unsigned*)&Bb[(size_t)(nt * 8 + g) * 36 + kc + t + 4];
                mma8(acc[nt][0], acc[nt][1], acc[nt][2], acc[nt][3],
                     a0, a1, a2, a3, b0, b1);
            }
        }
        __syncthreads();
    }

    // ---- epilogue: +t[j], col expsums, row softmax -> S1, row sums -> rs ----
    float* S1b = g_S1 + (size_t)b * LCC * LQQ;
    float cs[16];
    #pragma unroll
    for (int c = 0; c < 16; c++) cs[c] = 0.f;

    #pragma unroll
    for (int h = 0; h < 2; h++) {
        const int i = i0 + wm + h * 8 + g;
        float s[16];
        #pragma unroll
        for (int nt = 0; nt < 8; nt++) {
            s[2 * nt]     = acc[nt][2 * h]     + ts[nt * 8 + 2 * t];
            s[2 * nt + 1] = acc[nt][2 * h + 1] + ts[nt * 8 + 2 * t + 1];
        }
        #pragma unroll
        for (int c = 0; c < 16; c++) cs[c] += __expf(s[c]);
        float m = s[0];
        #pragma unroll
        for (int c = 1; c < 16; c++) m = fmaxf(m, s[c]);
        m = fmaxf(m, __shfl_xor_sync(0xffffffffu, m, 1));
        m = fmaxf(m, __shfl_xor_sync(0xffffffffu, m, 2));
        float e[16], sum = 0.f;
        #pragma unroll
        for (int c = 0; c < 16; c++) { e[c] = __expf(s[c] - m); sum += e[c]; }
        sum += __shfl_xor_sync(0xffffffffu, sum, 1);
        sum += __shfl_xor_sync(0xffffffffu, sum, 2);
        const float inv = 1.f / sum;
        #pragma unroll
        for (int nt = 0; nt < 8; nt++) {
            float2 o = make_float2(e[2 * nt] * inv, e[2 * nt + 1] * inv);
            *(float2*)&S1b[(size_t)i * LQQ + nt * 8 + 2 * t] = o;
        }
        if (t == 0) g_rs[b * LCC + i] = sum * __expf(m);
    }
    #pragma unroll
    for (int c = 0; c < 16; c++) {
        cs[c] += __shfl_xor_sync(0xffffffffu, cs[c], 4);
        cs[c] += __shfl_xor_sync(0xffffffffu, cs[c], 8);
        cs[c] += __shfl_xor_sync(0xffffffffu, cs[c], 16);
    }
    if (g == 0) {
        #pragma unroll
        for (int c = 0; c < 16; c++) {
            const int j = (c >> 1) * 8 + 2 * t + (c & 1);
            scol[warp * 64 + j] = cs[c];
        }
    }
    __syncthreads();
    if (tid < 64) {
        float p = 0.f;
        #pragma unroll
        for (int w = 0; w < 8; w++) p += scol[w * 64 + tid];
        g_cpart[blockIdx.x * (BB * LQQ) + b * LQQ + tid] = p;
    }
}

// ---------------------------------------------------------------------------
// K3: C2 = S2^T @ contex, full K=512.  S2[i,j] = S1[i,j]*rs_i*inv_j built on
// the A-fill from L2-hot S1 (no exp).  inv combine folded into prologue.
// Block 64(j) x 64(n), 512 thr = 16 warps 4(m)x4(n), warp tile 16x16.
// A stored [k][j] so the transpose-fill is one float4 STS. grid=(4, B)
// ---------------------------------------------------------------------------
__global__ void __launch_bounds__(512, 2) k3_c2(const float* __restrict__ contex) {
    const int b   = blockIdx.y;
    const int n0  = blockIdx.x * 64;
    const int tid = threadIdx.x;
    const int warp = tid >> 5, lane = tid & 31;
    const int g = lane >> 2, t = lane & 3;
    const int wm = (warp & 3) * 16;
    const int wn = (warp >> 2) * 16;

    extern __shared__ float sm3[];
    float* As   = sm3;                     // 2 x 32 x 68 [k=i][j]
    float* Bs   = sm3 + 4352;              // 3 x 32 x 72 [k][n]
    float* rssm = sm3 + 4352 + 6912;       // 512
    float* sinv = rssm + 512;              // 64

    const float* S1b = g_S1 + (size_t)b * LCC * LQQ;
    const float* Cb  = contex + (size_t)b * LCC * DD;

    rssm[tid] = g_rs[b * LCC + tid];
    if (tid < 64) {
        const int idx = b * LQQ + tid;
        float s = g_cpart[idx] + g_cpart[BB * LQQ + idx]
                + g_cpart[2 * BB * LQQ + idx] + g_cpart[3 * BB * LQQ + idx];
        sinv[tid] = 1.f / s;
    }
    __syncthreads();

    const int iloc = tid >> 4, jo = (tid & 15) * 4;   // A fill: 32 rows x 64 j
    const float4 inv4 = *(const float4*)&sinv[jo];
    const unsigned smu = sm2u(sm3);

    auto cpB = [&](int s) {
        const int buf = s % 3;
        const float* c = &Cb[(size_t)(s * 32 + iloc) * DD + n0 + jo];
        unsigned db = smu + (unsigned)(4352 + (buf * 32 + iloc) * 72 + jo) * 4u;
        CPA16(db, c);
        CPCOMMIT();
    };

    float4 ra; float rsv;
    auto ldA = [&](int s) {
        ra  = *(const float4*)&S1b[(size_t)(s * 32 + iloc) * LQQ + jo];
        rsv = rssm[s * 32 + iloc];
    };
    auto stA = [&](int s) {
        float4 v = make_float4(ra.x * rsv * inv4.x, ra.y * rsv * inv4.y,
                               ra.z * rsv * inv4.z, ra.w * rsv * inv4.w);
        *(float4*)&As[(size_t)((s & 1) * 32 + iloc) * 68 + jo] = v;
    };

    float acc[2][4];
    #pragma unroll
    for (int nt = 0; nt < 2; nt++)
        #pragma unroll
        for (int r = 0; r < 4; r++) acc[nt][r] = 0.f;

    cpB(0); cpB(1);
    ldA(0); stA(0);

    #pragma unroll 4
    for (int it = 0; it < 16; it++) {
        if (it < 15) { CPWAIT1(); } else { CPWAIT0(); }
        __syncthreads();
        if (it + 2 < 16) cpB(it + 2);
        if (it < 15) ldA(it + 1);

        const float* Ab = As + (size_t)(it & 1) * 32 * 68;
        const float* Bb = Bs + (size_t)(it % 3) * 32 * 72;
        #pragma unroll
        for (int kc = 0; kc < 32; kc += 8) {
            unsigned a0 = *(const unsigned*)&Ab[(size_t)(kc + t) * 68 + wm + g];
            unsigned a1 = *(const unsigned*)&Ab[(size_t)(kc + t) * 68 + wm + 8 + g];
            unsigned a2 = *(const unsigned*)&Ab[(size_t)(kc + t + 4) * 68 + wm + g];
            unsigned a3 = *(const unsigned*)&Ab[(size_t)(kc + t + 4) * 68 + wm + 8 + g];
            #pragma unroll
            for (int nt = 0; nt < 2; nt++) {
                const int n = wn + nt * 8 + g;
                unsigned b0 = *(const unsigned*)&Bb[(size_t)(kc + t) * 72 + n];
                unsigned b1 = *(const unsigned*)&Bb[(size_t)(kc + t + 4) * 72 + n];
                mma8(acc[nt][0], acc[nt][1], acc[nt][2], acc[nt][3],
                     a0, a1, a2, a3, b0, b1);
            }
        }
        if (it < 15) stA(it + 1);
        __syncthreads();
    }

    float* outp = g_C2 + (size_t)b * LQQ * DD;
    #pragma unroll
    for (int h = 0; h < 2; h++) {
        const int j = wm + h * 8 + g;
        #pragma unroll
        for (int nt = 0; nt < 2; nt++) {
            float2 o = make_float2(acc[nt][2 * h], acc[nt][2 * h + 1]);
            *(float2*)&outp[(size_t)j * DD + n0 + wn + nt * 8 + 2 * t] = o;
        }
    }
}

// ---------------------------------------------------------------------------
// K4: A = S1 @ question, Bm = S1 @ C2, dual-B per chunk via 2-stage cp.async.
// Block 64(i), 256 thr = 8 warps 4(m)x2(n). Epilogue stages fragments in the
// consumed B-buffer smem, then writes contex/A/cA/cBm with fully coalesced
// LDG.128/STG.128 (2 rows x 256B per warp-instruction). grid=(8, B)
// ---------------------------------------------------------------------------
__global__ void __launch_bounds__(256, 2) k4_out(const float* __restrict__ contex,
                                                 const float* __restrict__ question,
                                                 float* __restrict__ out) {
    const int b  = blockIdx.y;
    const int i0 = blockIdx.x * 64;
    const int tid = threadIdx.x;
    const int warp = tid >> 5, lane = tid & 31;
    const int g = lane >> 2, t = lane & 3;
    const int wm = (warp & 3) * 16;
    const int wn = (warp >> 2) * 32;

    extern __shared__ float sm4[];
    float* As = sm4;                        // 64 x 68 [i][j] persistent
    float* Bt = sm4 + 64 * 68;              // 2 buf x (2 tiles x 64 x 72)

    const float* S1b = g_S1 + (size_t)b * LCC * LQQ;
    {   // fill A once (raw fp32): 64 rows x 64 j
        const int lr = tid >> 2, jo = (tid & 3) * 16;
        const float* src = &S1b[(size_t)(i0 + lr) * LQQ + jo];
        float* dst = &As[(size_t)lr * 68 + jo];
        *(float4*)&dst[0]  = *(const float4*)&src[0];
        *(float4*)&dst[4]  = *(const float4*)&src[4];
        *(float4*)&dst[8]  = *(const float4*)&src[8];
        *(float4*)&dst[12] = *(const float4*)&src[12];
    }

    const float* Cb = contex   + (size_t)b * LCC * DD;
    const float* Qb = question + (size_t)b * LQQ * DD;
    const float* P  = g_C2     + (size_t)b * LQQ * DD;
    float* outb = out + (size_t)b * LCC * 1024;

    const int bjr = tid >> 2, boff = (tid & 3) * 16;   // 64 rows x 4 thr/row
    const unsigned smu = sm2u(sm4);

    auto cpB = [&](int chunk) {
        const int buf = chunk & 1;
        const int c0 = chunk * 64;
        const float* q = &Qb[(size_t)bjr * DD + c0 + boff];
        unsigned dq = smu + (unsigned)(64 * 68 + (buf * 128 + bjr) * 72 + boff) * 4u;
        CPA16(dq,      q);     CPA16(dq + 16, q + 4);
        CPA16(dq + 32, q + 8); CPA16(dq + 48, q + 12);
        const float* p = &P[(size_t)bjr * DD + c0 + boff];
        unsigned dc = smu + (unsigned)(64 * 68 + (buf * 128 + 64 + bjr) * 72 + boff) * 4u;
        CPA16(dc,      p);     CPA16(dc + 16, p + 4);
        CPA16(dc + 32, p + 8); CPA16(dc + 48, p + 12);
        CPCOMMIT();
    };

    cpB(0);

    const int orw = tid >> 4;              // 0..15 (epilogue row within pass)
    const int occ4 = (tid & 15) * 4;       // 0..60 (epilogue col)

    #pragma unroll
    for (int chunk = 0; chunk < 4; chunk++) {
        const int buf = chunk & 1;
        const int c0 = chunk * 64;
        if (chunk < 3) cpB(chunk + 1);
        if (chunk < 3) { CPWAIT1(); } else { CPWAIT0(); }
        __syncthreads();

        float accq[4][4], accc[4][4];
        #pragma unroll
        for (int nt = 0; nt < 4; nt++)
            #pragma unroll
            for (int r = 0; r < 4; r++) { accq[nt][r] = 0.f; accc[nt][r] = 0.f; }

        const float* Bq = Bt + (size_t)buf * 9216;
        const float* Bc = Bq + 64 * 72;
        #pragma unroll
        for (int kc = 0; kc < 64; kc += 8) {
            unsigned a0 = *(const unsigned*)&As[(size_t)(wm + g) * 68 + kc + t];
            unsigned a1 = *(const unsigned*)&As[(size_t)(wm + 8 + g) * 68 + kc + t];
            unsigned a2 = *(const unsigned*)&As[(size_t)(wm + g) * 68 + kc + t + 4];
            unsigned a3 = *(const unsigned*)&As[(size_t)(wm + 8 + g) * 68 + kc + t + 4];
            #pragma unroll
            for (int nt = 0; nt < 4; nt++) {
                const int n = wn + nt * 8 + g;
                unsigned q0 = *(const unsigned*)&Bq[(size_t)(kc + t) * 72 + n];
                unsigned q1 = *(const unsigned*)&Bq[(size_t)(kc + t + 4) * 72 + n];
                mma8(accq[nt][0], accq[nt][1], accq[nt][2], accq[nt][3],
                     a0, a1, a2, a3, q0, q1);
                unsigned c0r = *(const unsigned*)&Bc[(size_t)(kc + t) * 72 + n];
                unsigned c1r = *(const unsigned*)&Bc[(size_t)(kc + t + 4) * 72 + n];
                mma8(accc[nt][0], accc[nt][1], accc[nt][2], accc[nt][3],
                     a0, a1, a2, a3, c0r, c1r);
            }
        }
        __syncthreads();   // all warps done reading buf -> safe to reuse as stage

        // stage fragments into consumed B buffer region: 2 tiles [64][68]
        float* stA_ = Bt + (size_t)buf * 9216;
        float* stC_ = stA_ + 4352;
        #pragma unroll
        for (int h = 0; h < 2; h++) {
            const int r = wm + h * 8 + g;
            #pragma unroll
            for (int nt = 0; nt < 4; nt++) {
                const int c = wn + nt * 8 + 2 * t;
                *(float2*)&stA_[(size_t)r * 68 + c] =
                    make_float2(accq[nt][2 * h], accq[nt][2 * h + 1]);
                *(float2*)&stC_[(size_t)r * 68 + c] =
                    make_float2(accc[nt][2 * h], accc[nt][2 * h + 1]);
            }
        }
        __syncthreads();

        // coalesced output: 4 passes x (LDG.128 contex + 4x STG.128)
        #pragma unroll
        for (int p = 0; p < 4; p++) {
            const int r = p * 16 + orw;
            float4 a4 = *(const float4*)&stA_[(size_t)r * 68 + occ4];
            float4 m4 = *(const float4*)&stC_[(size_t)r * 68 + occ4];
            float4 cv = *(const float4*)&Cb[(size_t)(i0 + r) * DD + c0 + occ4];
            float4 pa = make_float4(cv.x * a4.x, cv.y * a4.y, cv.z * a4.z, cv.w * a4.w);
            float4 pb = make_float4(cv.x * m4.x, cv.y * m4.y, cv.z * m4.z, cv.w * m4.w);
            float* orow = &outb[(size_t)(i0 + r) * 1024 + c0 + occ4];
            *(float4*)&orow[0]   = cv;   // contex
            *(float4*)&orow[256] = a4;   // A
            *(float4*)&orow[512] = pa;   // contex * A
            *(float4*)&orow[768] = pb;   // contex * Bm
        }
        __syncthreads();   // stage reads done before next cp.async reuses region
    }
}

// ---------------------------------------------------------------------------
extern "C" void kernel_launch(void* const* d_in, const int* in_sizes, int n_in,
                              void* d_out, int out_size) {
    const float* contex   = (const float*)d_in[0];
    const float* question = (const float*)d_in[1];
    const float* W        = (const float*)d_in[2];
    const float* bias     = (const float*)d_in[3];
    float* out = (float*)d_out;

    const int k1smem = 21312 * (int)sizeof(float);                          // 85248
    const int k3smem = (4352 + 6912 + 512 + 64) * (int)sizeof(float);       // 47360
    const int k4smem = (64 * 68 + 2 * 2 * 64 * 72) * (int)sizeof(float);    // 91136
    cudaFuncSetAttribute(k1_score, cudaFuncAttributeMaxDynamicSharedMemorySize, k1smem);
    cudaFuncSetAttribute(k3_c2,    cudaFuncAttributeMaxDynamicSharedMemorySize, k3smem);
    cudaFuncSetAttribute(k4_out,   cudaFuncAttributeMaxDynamicSharedMemorySize, k4smem);

    k0_prep<<<BB * LQQ, 256>>>(question, W, bias);
    k1_score<<<dim3(4, BB), 256, k1smem>>>(contex);
    k3_c2<<<dim3(4, BB), 512, k3smem>>>(contex);
    k4_out<<<dim3(8, BB), 256, k4smem>>>(contex, question, out);
}

// round 12
// speedup vs baseline: 1.1134x; 1.1060x over previous
#include <cuda_runtime.h>
#include <math.h>

#define BB  64
#define LCC 512
#define LQQ 64
#define DD  256

// ---------------------------------------------------------------------------
// tf32 mma (m16n8k8, row.col, fp32 accum) — operands are RAW fp32 bits
// ---------------------------------------------------------------------------
__device__ __forceinline__ void mma8(float& d0, float& d1, float& d2, float& d3,
                                     unsigned a0, unsigned a1, unsigned a2, unsigned a3,
                                     unsigned b0, unsigned b1) {
    asm("mma.sync.aligned.m16n8k8.row.col.f32.tf32.tf32.f32 "
        "{%0,%1,%2,%3},{%4,%5,%6,%7},{%8,%9},{%0,%1,%2,%3};"
        : "+f"(d0), "+f"(d1), "+f"(d2), "+f"(d3)
        : "r"(a0), "r"(a1), "r"(a2), "r"(a3), "r"(b0), "r"(b1));
}
__device__ __forceinline__ unsigned sm2u(const void* p) {
    unsigned r;
    asm("{.reg .u64 t; cvta.to.shared.u64 t, %1; cvt.u32.u64 %0, t;}" : "=r"(r) : "l"(p));
    return r;
}
__device__ __forceinline__ void stg_cs(float* p, float4 v) {
    asm volatile("st.global.cs.v4.f32 [%0], {%1,%2,%3,%4};"
                 :: "l"(p), "f"(v.x), "f"(v.y), "f"(v.z), "f"(v.w));
}
#define CPA16(dst, src) asm volatile("cp.async.ca.shared.global [%0], [%1], 16;" :: "r"(dst), "l"(src))
#define CPCOMMIT()      asm volatile("cp.async.commit_group;")
#define CPWAIT1()       asm volatile("cp.async.wait_group 1;")
#define CPWAIT0()       asm volatile("cp.async.wait_group 0;")

// Scratch (device globals; no allocation allowed)
__device__ float g_Qp[(size_t)BB * LQQ * DD];            // wi*q + wc
__device__ float g_t[BB * LQQ];                          // <q,wq> + bias
__device__ float g_S1[(size_t)BB * LCC * LQQ];           // row-softmax(S)
__device__ float g_rs[BB * LCC];                         // unshifted row expsums
__device__ float g_cpart[4 * BB * LQQ];                  // per-i-block col expsum partials
__device__ float g_C2[(size_t)BB * LQQ * DD];            // S2^T @ contex

// ---------------------------------------------------------------------------
// K0: Q'[b,j,d] = wi[d]*q[b,j,d] + wc[d];  t[b,j] = <q[b,j], wq> + bias
// ---------------------------------------------------------------------------
__global__ void k0_prep(const float* __restrict__ q,
                        const float* __restrict__ W,
                        const float* __restrict__ bias) {
    const int bj = blockIdx.x;
    const int d  = threadIdx.x;
    const float qv = q[(size_t)bj * DD + d];
    g_Qp[(size_t)bj * DD + d] = fmaf(W[2 * DD + d], qv, W[DD + d]);

    float v = qv * W[d];
    #pragma unroll
    for (int o = 16; o > 0; o >>= 1) v += __shfl_xor_sync(0xffffffffu, v, o);
    __shared__ float red[8];
    if ((threadIdx.x & 31) == 0) red[threadIdx.x >> 5] = v;
    __syncthreads();
    if (threadIdx.x == 0) {
        float s = 0.f;
        #pragma unroll
        for (int i = 0; i < 8; i++) s += red[i];
        g_t[bj] = s + bias[0];
    }
}

// ---------------------------------------------------------------------------
// K1: S = contex @ Q'^T + t via raw-fp32 tf32 mma, 3-stage cp.async pipeline.
// Block 128(i) x 64(j), 256 thr = 8 warps (16x64), K=256. grid=(4, B)
// Outputs: S1 (row softmax), rs (row expsums), col expsum partials.
// ---------------------------------------------------------------------------
__global__ void __launch_bounds__(256, 2) k1_score(const float* __restrict__ contex) {
    const int b  = blockIdx.y;
    const int i0 = blockIdx.x * 128;
    const int tid = threadIdx.x;
    const int warp = tid >> 5, lane = tid & 31;
    const int g = lane >> 2, t = lane & 3;
    const int wm = warp * 16;

    extern __shared__ float sm[];
    float* As   = sm;                 // 3 x 128 x 36 = 13824
    float* Bs   = sm + 13824;         // 3 x 64 x 36  = 6912
    float* ts   = sm + 20736;         // 64
    float* scol = sm + 20800;         // 8 x 64 = 512
    if (tid < 64) ts[tid] = g_t[b * LQQ + tid];

    const float* Cb = contex + (size_t)b * LCC * DD;
    const float* Qp = g_Qp  + (size_t)b * LQQ * DD;

    const int alr = tid >> 1, ako = (tid & 1) * 16;   // A: 4x16B per stage
    const int bjr = tid >> 2, bko = (tid & 3) * 8;    // B: 2x16B per stage
    const unsigned smu = sm2u(sm);

    auto cpStage = [&](int s) {
        const int buf = s % 3;
        const float* ga = &Cb[(size_t)(i0 + alr) * DD + s * 32 + ako];
        unsigned da = smu + (unsigned)((buf * 128 + alr) * 36 + ako) * 4u;
        CPA16(da,      ga);     CPA16(da + 16, ga + 4);
        CPA16(da + 32, ga + 8); CPA16(da + 48, ga + 12);
        const float* gb = &Qp[(size_t)bjr * DD + s * 32 + bko];
        unsigned db = smu + (unsigned)(13824 + (buf * 64 + bjr) * 36 + bko) * 4u;
        CPA16(db, gb); CPA16(db + 16, gb + 4);
        CPCOMMIT();
    };

    float acc[8][4];
    #pragma unroll
    for (int nt = 0; nt < 8; nt++)
        #pragma unroll
        for (int r = 0; r < 4; r++) acc[nt][r] = 0.f;

    cpStage(0); cpStage(1);

    #pragma unroll
    for (int it = 0; it < 8; it++) {
        if (it < 7) { CPWAIT1(); } else { CPWAIT0(); }
        __syncthreads();
        if (it + 2 < 8) cpStage(it + 2);
        const float* Ab = As + (size_t)(it % 3) * 128 * 36;
        const float* Bb = Bs + (size_t)(it % 3) * 64 * 36;
        #pragma unroll
        for (int kc = 0; kc < 32; kc += 8) {
            unsigned a0 = *(const unsigned*)&Ab[(size_t)(wm + g) * 36 + kc + t];
            unsigned a1 = *(const unsigned*)&Ab[(size_t)(wm + 8 + g) * 36 + kc + t];
            unsigned a2 = *(const unsigned*)&Ab[(size_t)(wm + g) * 36 + kc + t + 4];
            unsigned a3 = *(const unsigned*)&Ab[(size_t)(wm + 8 + g) * 36 + kc + t + 4];
            #pragma unroll
            for (int nt = 0; nt < 8; nt++) {
                unsigned b0 = *(const unsigned*)&Bb[(size_t)(nt * 8 + g) * 36 + kc + t];
                unsigned b1 = *(const unsigned*)&Bb[(size_t)(nt * 8 + g) * 36 + kc + t + 4];
                mma8(acc[nt][0], acc[nt][1], acc[nt][2], acc[nt][3],
                     a0, a1, a2, a3, b0, b1);
            }
        }
        __syncthreads();
    }

    // ---- epilogue: +t[j], col expsums, row softmax -> S1, row sums -> rs ----
    float* S1b = g_S1 + (size_t)b * LCC * LQQ;
    float cs[16];
    #pragma unroll
    for (int c = 0; c < 16; c++) cs[c] = 0.f;

    #pragma unroll
    for (int h = 0; h < 2; h++) {
        const int i = i0 + wm + h * 8 + g;
        float s[16];
        #pragma unroll
        for (int nt = 0; nt < 8; nt++) {
            s[2 * nt]     = acc[nt][2 * h]     + ts[nt * 8 + 2 * t];
            s[2 * nt + 1] = acc[nt][2 * h + 1] + ts[nt * 8 + 2 * t + 1];
        }
        #pragma unroll
        for (int c = 0; c < 16; c++) cs[c] += __expf(s[c]);
        float m = s[0];
        #pragma unroll
        for (int c = 1; c < 16; c++) m = fmaxf(m, s[c]);
        m = fmaxf(m, __shfl_xor_sync(0xffffffffu, m, 1));
        m = fmaxf(m, __shfl_xor_sync(0xffffffffu, m, 2));
        float e[16], sum = 0.f;
        #pragma unroll
        for (int c = 0; c < 16; c++) { e[c] = __expf(s[c] - m); sum += e[c]; }
        sum += __shfl_xor_sync(0xffffffffu, sum, 1);
        sum += __shfl_xor_sync(0xffffffffu, sum, 2);
        const float inv = 1.f / sum;
        #pragma unroll
        for (int nt = 0; nt < 8; nt++) {
            float2 o = make_float2(e[2 * nt] * inv, e[2 * nt + 1] * inv);
            *(float2*)&S1b[(size_t)i * LQQ + nt * 8 + 2 * t] = o;
        }
        if (t == 0) g_rs[b * LCC + i] = sum * __expf(m);
    }
    #pragma unroll
    for (int c = 0; c < 16; c++) {
        cs[c] += __shfl_xor_sync(0xffffffffu, cs[c], 4);
        cs[c] += __shfl_xor_sync(0xffffffffu, cs[c], 8);
        cs[c] += __shfl_xor_sync(0xffffffffu, cs[c], 16);
    }
    if (g == 0) {
        #pragma unroll
        for (int c = 0; c < 16; c++) {
            const int j = (c >> 1) * 8 + 2 * t + (c & 1);
            scol[warp * 64 + j] = cs[c];
        }
    }
    __syncthreads();
    if (tid < 64) {
        float p = 0.f;
        #pragma unroll
        for (int w = 0; w < 8; w++) p += scol[w * 64 + tid];
        g_cpart[blockIdx.x * (BB * LQQ) + b * LQQ + tid] = p;
    }
}

// ---------------------------------------------------------------------------
// K3: C2 = S2^T @ contex, full K=512.  S2[i,j] = S1[i,j]*rs_i*inv_j built on
// the A-fill from L2-hot S1 (no exp).  inv combine folded into prologue.
// Block 64(j) x 64(n), 512 thr = 16 warps 4(m)x4(n), warp tile 16x16.
// A stored [k][j] so the transpose-fill is one float4 STS. grid=(4, B)
// ---------------------------------------------------------------------------
__global__ void __launch_bounds__(512, 2) k3_c2(const float* __restrict__ contex) {
    const int b   = blockIdx.y;
    const int n0  = blockIdx.x * 64;
    const int tid = threadIdx.x;
    const int warp = tid >> 5, lane = tid & 31;
    const int g = lane >> 2, t = lane & 3;
    const int wm = (warp & 3) * 16;
    const int wn = (warp >> 2) * 16;

    extern __shared__ float sm3[];
    float* As   = sm3;                     // 2 x 32 x 68 [k=i][j]
    float* Bs   = sm3 + 4352;              // 3 x 32 x 72 [k][n]
    float* rssm = sm3 + 4352 + 6912;       // 512
    float* sinv = rssm + 512;              // 64

    const float* S1b = g_S1 + (size_t)b * LCC * LQQ;
    const float* Cb  = contex + (size_t)b * LCC * DD;

    rssm[tid] = g_rs[b * LCC + tid];
    if (tid < 64) {
        const int idx = b * LQQ + tid;
        float s = g_cpart[idx] + g_cpart[BB * LQQ + idx]
                + g_cpart[2 * BB * LQQ + idx] + g_cpart[3 * BB * LQQ + idx];
        sinv[tid] = 1.f / s;
    }
    __syncthreads();

    const int iloc = tid >> 4, jo = (tid & 15) * 4;   // A fill: 32 rows x 64 j
    const float4 inv4 = *(const float4*)&sinv[jo];
    const unsigned smu = sm2u(sm3);

    auto cpB = [&](int s) {
        const int buf = s % 3;
        const float* c = &Cb[(size_t)(s * 32 + iloc) * DD + n0 + jo];
        unsigned db = smu + (unsigned)(4352 + (buf * 32 + iloc) * 72 + jo) * 4u;
        CPA16(db, c);
        CPCOMMIT();
    };

    float4 ra; float rsv;
    auto ldA = [&](int s) {
        ra  = *(const float4*)&S1b[(size_t)(s * 32 + iloc) * LQQ + jo];
        rsv = rssm[s * 32 + iloc];
    };
    auto stA = [&](int s) {
        float4 v = make_float4(ra.x * rsv * inv4.x, ra.y * rsv * inv4.y,
                               ra.z * rsv * inv4.z, ra.w * rsv * inv4.w);
        *(float4*)&As[(size_t)((s & 1) * 32 + iloc) * 68 + jo] = v;
    };

    float acc[2][4];
    #pragma unroll
    for (int nt = 0; nt < 2; nt++)
        #pragma unroll
        for (int r = 0; r < 4; r++) acc[nt][r] = 0.f;

    cpB(0); cpB(1);
    ldA(0); stA(0);

    #pragma unroll 4
    for (int it = 0; it < 16; it++) {
        if (it < 15) { CPWAIT1(); } else { CPWAIT0(); }
        __syncthreads();
        if (it + 2 < 16) cpB(it + 2);
        if (it < 15) ldA(it + 1);

        const float* Ab = As + (size_t)(it & 1) * 32 * 68;
        const float* Bb = Bs + (size_t)(it % 3) * 32 * 72;
        #pragma unroll
        for (int kc = 0; kc < 32; kc += 8) {
            unsigned a0 = *(const unsigned*)&Ab[(size_t)(kc + t) * 68 + wm + g];
            unsigned a1 = *(const unsigned*)&Ab[(size_t)(kc + t) * 68 + wm + 8 + g];
            unsigned a2 = *(const unsigned*)&Ab[(size_t)(kc + t + 4) * 68 + wm + g];
            unsigned a3 = *(const unsigned*)&Ab[(size_t)(kc + t + 4) * 68 + wm + 8 + g];
            #pragma unroll
            for (int nt = 0; nt < 2; nt++) {
                const int n = wn + nt * 8 + g;
                unsigned b0 = *(const unsigned*)&Bb[(size_t)(kc + t) * 72 + n];
                unsigned b1 = *(const unsigned*)&Bb[(size_t)(kc + t + 4) * 72 + n];
                mma8(acc[nt][0], acc[nt][1], acc[nt][2], acc[nt][3],
                     a0, a1, a2, a3, b0, b1);
            }
        }
        if (it < 15) stA(it + 1);
        __syncthreads();
    }

    float* outp = g_C2 + (size_t)b * LQQ * DD;
    #pragma unroll
    for (int h = 0; h < 2; h++) {
        const int j = wm + h * 8 + g;
        #pragma unroll
        for (int nt = 0; nt < 2; nt++) {
            float2 o = make_float2(acc[nt][2 * h], acc[nt][2 * h + 1]);
            *(float2*)&outp[(size_t)j * DD + n0 + wn + nt * 8 + 2 * t] = o;
        }
    }
}

// ---------------------------------------------------------------------------
// K4: one (i-block, chunk) per CTA — chunk loop moved into the grid for
// block-level latency hiding. A = S1 @ question, Bm = S1 @ C2 (K=64);
// fused output out[b,i] = [contex | A | contex*A | contex*Bm] with
// smem-staged fragments and st.global.cs streaming stores. grid=(8, B, 4)
// ---------------------------------------------------------------------------
__global__ void __launch_bounds__(256) k4_out(const float* __restrict__ contex,
                                              const float* __restrict__ question,
                                              float* __restrict__ out) {
    const int b   = blockIdx.y;
    const int i0  = blockIdx.x * 64;
    const int c0  = blockIdx.z * 64;
    const int tid = threadIdx.x;
    const int warp = tid >> 5, lane = tid & 31;
    const int g = lane >> 2, t = lane & 3;
    const int wm = (warp & 3) * 16;
    const int wn = (warp >> 2) * 32;

    extern __shared__ float sm4[];
    float* As = sm4;                        // 64 x 68 [i][j]
    float* Bq = sm4 + 64 * 68;              // 64 x 72 [j][n]  (question chunk)
    float* Bc = Bq + 64 * 72;               // 64 x 72 [j][n]  (C2 chunk)

    const float* S1b = g_S1 + (size_t)b * LCC * LQQ;
    const float* Cb  = contex   + (size_t)b * LCC * DD;
    const float* Qb  = question + (size_t)b * LQQ * DD;
    const float* P   = g_C2     + (size_t)b * LQQ * DD;
    float* outb = out + (size_t)b * LCC * 1024;

    const unsigned smu = sm2u(sm4);
    {   // one cp.async group: A tile + both B tiles
        const int lr = tid >> 2, o16 = (tid & 3) * 16;
        const float* sa = &S1b[(size_t)(i0 + lr) * LQQ + o16];
        unsigned da = smu + (unsigned)(lr * 68 + o16) * 4u;
        CPA16(da, sa); CPA16(da + 16, sa + 4); CPA16(da + 32, sa + 8); CPA16(da + 48, sa + 12);
        const float* q = &Qb[(size_t)lr * DD + c0 + o16];
        unsigned dq = smu + (unsigned)(64 * 68 + lr * 72 + o16) * 4u;
        CPA16(dq, q); CPA16(dq + 16, q + 4); CPA16(dq + 32, q + 8); CPA16(dq + 48, q + 12);
        const float* p = &P[(size_t)lr * DD + c0 + o16];
        unsigned dc = smu + (unsigned)(64 * 68 + 64 * 72 + lr * 72 + o16) * 4u;
        CPA16(dc, p); CPA16(dc + 16, p + 4); CPA16(dc + 32, p + 8); CPA16(dc + 48, p + 12);
        CPCOMMIT();
    }
    CPWAIT0();
    __syncthreads();

    float accq[4][4], accc[4][4];
    #pragma unroll
    for (int nt = 0; nt < 4; nt++)
        #pragma unroll
        for (int r = 0; r < 4; r++) { accq[nt][r] = 0.f; accc[nt][r] = 0.f; }

    #pragma unroll
    for (int kc = 0; kc < 64; kc += 8) {
        unsigned a0 = *(const unsigned*)&As[(size_t)(wm + g) * 68 + kc + t];
        unsigned a1 = *(const unsigned*)&As[(size_t)(wm + 8 + g) * 68 + kc + t];
        unsigned a2 = *(const unsigned*)&As[(size_t)(wm + g) * 68 + kc + t + 4];
        unsigned a3 = *(const unsigned*)&As[(size_t)(wm + 8 + g) * 68 + kc + t + 4];
        #pragma unroll
        for (int nt = 0; nt < 4; nt++) {
            const int n = wn + nt * 8 + g;
            unsigned q0 = *(const unsigned*)&Bq[(size_t)(kc + t) * 72 + n];
            unsigned q1 = *(const unsigned*)&Bq[(size_t)(kc + t + 4) * 72 + n];
            mma8(accq[nt][0], accq[nt][1], accq[nt][2], accq[nt][3],
                 a0, a1, a2, a3, q0, q1);
            unsigned c0r = *(const unsigned*)&Bc[(size_t)(kc + t) * 72 + n];
            unsigned c1r = *(const unsigned*)&Bc[(size_t)(kc + t + 4) * 72 + n];
            mma8(accc[nt][0], accc[nt][1], accc[nt][2], accc[nt][3],
                 a0, a1, a2, a3, c0r, c1r);
        }
    }
    __syncthreads();   // B tiles consumed -> reuse as fragment stage

    // stage fragments: Bq region holds A-frags, Bc region holds Bm-frags
    #pragma unroll
    for (int h = 0; h < 2; h++) {
        const int r = wm + h * 8 + g;
        #pragma unroll
        for (int nt = 0; nt < 4; nt++) {
            const int c = wn + nt * 8 + 2 * t;
            *(float2*)&Bq[(size_t)r * 72 + c] =
                make_float2(accq[nt][2 * h], accq[nt][2 * h + 1]);
            *(float2*)&Bc[(size_t)r * 72 + c] =
                make_float2(accc[nt][2 * h], accc[nt][2 * h + 1]);
        }
    }
    __syncthreads();

    // coalesced output: 4 passes x (LDG.128 contex + 4x STG.128.cs)
    const int orw = tid >> 4;              // 0..15
    const int occ4 = (tid & 15) * 4;       // 0..60
    #pragma unroll
    for (int p = 0; p < 4; p++) {
        const int r = p * 16 + orw;
        float4 a4 = *(const float4*)&Bq[(size_t)r * 72 + occ4];
        float4 m4 = *(const float4*)&Bc[(size_t)r * 72 + occ4];
        float4 cv = *(const float4*)&Cb[(size_t)(i0 + r) * DD + c0 + occ4];
        float4 pa = make_float4(cv.x * a4.x, cv.y * a4.y, cv.z * a4.z, cv.w * a4.w);
        float4 pb = make_float4(cv.x * m4.x, cv.y * m4.y, cv.z * m4.z, cv.w * m4.w);
        float* orow = &outb[(size_t)(i0 + r) * 1024 + c0 + occ4];
        stg_cs(orow,       cv);   // contex
        stg_cs(orow + 256, a4);   // A
        stg_cs(orow + 512, pa);   // contex * A
        stg_cs(orow + 768, pb);   // contex * Bm
    }
}

// ---------------------------------------------------------------------------
extern "C" void kernel_launch(void* const* d_in, const int* in_sizes, int n_in,
                              void* d_out, int out_size) {
    const float* contex   = (const float*)d_in[0];
    const float* question = (const float*)d_in[1];
    const float* W        = (const float*)d_in[2];
    const float* bias     = (const float*)d_in[3];
    float* out = (float*)d_out;

    const int k1smem = 21312 * (int)sizeof(float);                          // 85248
    const int k3smem = (4352 + 6912 + 512 + 64) * (int)sizeof(float);       // 47360
    const int k4smem = (64 * 68 + 2 * 64 * 72) * (int)sizeof(float);        // 54272
    cudaFuncSetAttribute(k1_score, cudaFuncAttributeMaxDynamicSharedMemorySize, k1smem);
    cudaFuncSetAttribute(k3_c2,    cudaFuncAttributeMaxDynamicSharedMemorySize, k3smem);
    cudaFuncSetAttribute(k4_out,   cudaFuncAttributeMaxDynamicSharedMemorySize, k4smem);

    k0_prep<<<BB * LQQ, 256>>>(question, W, bias);
    k1_score<<<dim3(4, BB), 256, k1smem>>>(contex);
    k3_c2<<<dim3(4, BB), 512, k3smem>>>(contex);
    k4_out<<<dim3(8, BB, 4), 256, k4smem>>>(contex, question, out);
}